// round 13
// baseline (speedup 1.0000x reference)
#include <cuda_runtime.h>
#include <cuda_bf16.h>

#define BB 512
#define SS 512
#define CC 96
#define NB 8                    // batches per CTA (one MMA N-tile)
#define FWD_THREADS 192         // 6 warps = 6 M-tiles of 16 states
#define SUP 100                 // u row pad (bf16 elements)
#define SEP 100                 // em row pad (f32 elements)

__device__ float g_num[BB];
__device__ float g_den[BB];

__device__ __forceinline__ float fast_rcp(float x) {
    float r;
    asm("rcp.approx.f32 %0, %1;" : "=f"(r) : "f"(x));
    return r;
}
__device__ __forceinline__ unsigned pack_bf16(float x, float y) {
    __nv_bfloat162 h = __floats2bfloat162_rn(x, y);
    return *reinterpret_cast<unsigned*>(&h);
}
__device__ __forceinline__ void mma_bf16(
    float& d0, float& d1, float& d2, float& d3,
    unsigned a0, unsigned a1, unsigned a2, unsigned a3,
    unsigned b0, unsigned b1)
{
    asm volatile(
        "mma.sync.aligned.m16n8k16.row.col.f32.bf16.bf16.f32 "
        "{%0,%1,%2,%3},{%4,%5,%6,%7},{%8,%9},{%0,%1,%2,%3};"
        : "+f"(d0), "+f"(d1), "+f"(d2), "+f"(d3)
        : "r"(a0), "r"(a1), "r"(a2), "r"(a3), "r"(b0), "r"(b1));
}

// =====================================================================
// Forward via tensor cores: grid 64 CTAs x 192 threads; each CTA owns
// 8 batches. Per step: Q[96x8] = expT^T[96x96] @ U[96x8] as 6 warps x
// 6 chained mma.m16n8k16 (A fragments static in registers), then
// u_new = Q * exp(em) * r in fp32 registers (each lane persistently
// owns 4 (state,batch) cells), stored to smem as bf16 for the next
// step's B fragments. One __syncthreads per step. Unnormalized exp
// domain: r_b = rcp(u[0][b]) published pre-reciprocated (ping-pong);
// S_b -= log(r_b) tracked exactly on warp-0 lanes 0..3.
// =====================================================================
__global__ __launch_bounds__(FWD_THREADS, 1) void crf_forward_kernel(
    const float* __restrict__ em,
    const int* __restrict__ masks,
    const float* __restrict__ start,
    const float* __restrict__ endt,
    const float* __restrict__ trans)
{
    __shared__ __nv_bfloat16 s_u[2][NB][SUP];
    __shared__ __align__(16) float s_em[2][NB][SEP];
    __shared__ float s_r[2][NB];
    __shared__ int   s_mk[2][NB];
    __shared__ float s_ee[CC];
    __shared__ float s_S[NB];

    const int tid  = threadIdx.x;
    const int mt   = tid >> 5;          // M-tile (16 states) this warp owns
    const int lane = tid & 31;
    const int lr   = lane >> 2;         // 0..7
    const int lc   = lane & 3;          // 0..3
    const int b0g  = blockIdx.x * NB;

    // D-fragment cells this lane owns forever:
    const int s0 = 16 * mt + lr, s1 = s0 + 8;     // states
    const int n0 = 2 * lc, n1 = n0 + 1;           // batches (CTA-local)

    // ---- A fragments: A[m][k] = exp(trans[k][m])  (A = expT^T, row-major)
    unsigned A[6][4];
#pragma unroll
    for (int kt = 0; kt < 6; kt++) {
        int k0 = 16 * kt + 2 * lc;
        int r0 = s0, r1 = s1;
        float a00 = __expf(trans[(k0 + 0) * CC + r0]);
        float a01 = __expf(trans[(k0 + 1) * CC + r0]);
        float a10 = __expf(trans[(k0 + 0) * CC + r1]);
        float a11 = __expf(trans[(k0 + 1) * CC + r1]);
        float a20 = __expf(trans[(k0 + 8) * CC + r0]);
        float a21 = __expf(trans[(k0 + 9) * CC + r0]);
        float a30 = __expf(trans[(k0 + 8) * CC + r1]);
        float a31 = __expf(trans[(k0 + 9) * CC + r1]);
        A[kt][0] = pack_bf16(a00, a01);
        A[kt][1] = pack_bf16(a10, a11);
        A[kt][2] = pack_bf16(a20, a21);
        A[kt][3] = pack_bf16(a30, a31);
    }

    // ---- t = 0: u = exp(start + em[.,0,.]) in fp32 regs + bf16 smem
    float u00 = __expf(start[s0] + em[(size_t)(b0g + n0) * SS * CC + s0]);
    float u01 = __expf(start[s0] + em[(size_t)(b0g + n1) * SS * CC + s0]);
    float u10 = __expf(start[s1] + em[(size_t)(b0g + n0) * SS * CC + s1]);
    float u11 = __expf(start[s1] + em[(size_t)(b0g + n1) * SS * CC + s1]);
    s_u[0][n0][s0] = __float2bfloat16(u00);
    s_u[0][n1][s0] = __float2bfloat16(u01);
    s_u[0][n0][s1] = __float2bfloat16(u10);
    s_u[0][n1][s1] = __float2bfloat16(u11);
    float S0 = 0.f, S1 = 0.f;
    if (mt == 0 && lr == 0) {
        s_r[0][n0] = fast_rcp(u00);
        s_r[0][n1] = fast_rcp(u01);
    }

    // stage em[1] (coalesced float4) and mask[1]
    const int sb = tid / 24, off4 = (tid % 24) * 4;
    *(float4*)&s_em[0][sb][off4] =
        *(const float4*)(em + (size_t)(b0g + sb) * SS * CC + 1 * CC + off4);
    if (tid < NB) s_mk[0][tid] = masks[(size_t)(b0g + tid) * SS + 1];
    if (tid < CC) s_ee[tid] = __expf(endt[tid]);
    __syncthreads();

    int p = 0, e = 0;
    for (int t = 1; t < SS; t++) {
        // B fragments from bf16 u of previous step
        unsigned B0[6], B1[6];
#pragma unroll
        for (int kt = 0; kt < 6; kt++) {
            const __nv_bfloat16* up = &s_u[p][lr][16 * kt + 2 * lc];
            B0[kt] = *(const unsigned*)up;
            B1[kt] = *(const unsigned*)(up + 8);
        }

        // stage em[t+1] / mask[t+1] into the other buffer
        int tn = (t + 1 < SS) ? t + 1 : t;
        float4 emv = *(const float4*)(em + (size_t)(b0g + sb) * SS * CC
                                      + (size_t)tn * CC + off4);
        int mkv = (tid < NB) ? masks[(size_t)(b0g + tid) * SS + tn] : 0;

        // Q = expT^T @ U  (6 chained MMAs, fp32 accum)
        float d0 = 0.f, d1 = 0.f, d2 = 0.f, d3 = 0.f;
#pragma unroll
        for (int kt = 0; kt < 6; kt++)
            mma_bf16(d0, d1, d2, d3,
                     A[kt][0], A[kt][1], A[kt][2], A[kt][3], B0[kt], B1[kt]);

        *(float4*)&s_em[e ^ 1][sb][off4] = emv;
        if (tid < NB) s_mk[e ^ 1][tid] = mkv;

        // epilogue: u_new = Q * exp(em) * r  (per owned cell)
        float E00 = __expf(s_em[e][n0][s0]);
        float E01 = __expf(s_em[e][n1][s0]);
        float E10 = __expf(s_em[e][n0][s1]);
        float E11 = __expf(s_em[e][n1][s1]);
        float r0 = s_r[p][n0], r1 = s_r[p][n1];
        int m0 = s_mk[e][n0], m1 = s_mk[e][n1];
        float v00 = d0 * (E00 * r0), v01 = d1 * (E01 * r1);
        float v10 = d2 * (E10 * r0), v11 = d3 * (E11 * r1);
        u00 = m0 ? v00 : u00;  u01 = m1 ? v01 : u01;
        u10 = m0 ? v10 : u10;  u11 = m1 ? v11 : u11;
        s_u[p ^ 1][n0][s0] = __float2bfloat16(u00);
        s_u[p ^ 1][n1][s0] = __float2bfloat16(u01);
        s_u[p ^ 1][n0][s1] = __float2bfloat16(u10);
        s_u[p ^ 1][n1][s1] = __float2bfloat16(u11);
        if (mt == 0 && lr == 0) {   // state 0 owners: publish normalizers
            s_r[p ^ 1][n0] = m0 ? fast_rcp(u00) : r0;
            s_r[p ^ 1][n1] = m1 ? fast_rcp(u01) : r1;
            S0 = m0 ? S0 - __logf(r0) : S0;
            S1 = m1 ? S1 - __logf(r1) : S1;
        }
        __syncthreads();
        p ^= 1;
        e ^= 1;
    }

    if (mt == 0 && lr == 0) { s_S[n0] = S0; s_S[n1] = S1; }
    __syncthreads();
    if (tid < NB) {
        float s = 0.f;
        for (int j = 0; j < CC; j++)
            s += __bfloat162float(s_u[p][tid][j]) * s_ee[j];
        g_den[b0g + tid] = s_S[tid] + __logf(s);
    }
}

// =====================================================================
// Numerator: one CTA (128 threads) per batch.
// =====================================================================
__global__ __launch_bounds__(128) void crf_num_kernel(
    const float* __restrict__ em,
    const int* __restrict__ tags,
    const int* __restrict__ masks,
    const float* __restrict__ start,
    const float* __restrict__ endt,
    const float* __restrict__ trans)
{
    const int b = blockIdx.x;
    const int tid = threadIdx.x;
    const int* tg = tags + (size_t)b * SS;
    const int* mk = masks + (size_t)b * SS;
    const float* e = em + (size_t)b * SS * CC;

    float s = 0.f;
    int cnt = 0;
#pragma unroll
    for (int it = 0; it < SS / 128; it++) {
        int t = tid + it * 128;
        int tagt = tg[t];
        int m = mk[t];
        cnt += m ? 1 : 0;
        if (t == 0) {
            s += start[tagt] + e[tagt];
        } else if (m) {
            int tp = tg[t - 1];
            s += trans[tp * CC + tagt] + e[(size_t)t * CC + tagt];
        }
    }
    __shared__ float ss[4];
    __shared__ int sc[4];
#pragma unroll
    for (int o = 16; o; o >>= 1) {
        s += __shfl_xor_sync(0xFFFFFFFFu, s, o);
        cnt += __shfl_xor_sync(0xFFFFFFFFu, cnt, o);
    }
    int wv = tid >> 5, lane = tid & 31;
    if (lane == 0) { ss[wv] = s; sc[wv] = cnt; }
    __syncthreads();
    if (tid == 0) {
        float st = ss[0] + ss[1] + ss[2] + ss[3];
        int ct = sc[0] + sc[1] + sc[2] + sc[3];
        int lt = tg[ct - 1];
        g_num[b] = st + endt[lt];
    }
}

// =====================================================================
// Final mean reduce
// =====================================================================
__global__ void crf_reduce_kernel(float* __restrict__ out)
{
    __shared__ float sh[BB];
    int t = threadIdx.x;
    sh[t] = g_num[t] - g_den[t];
    __syncthreads();
#pragma unroll
    for (int o = BB / 2; o > 0; o >>= 1) {
        if (t < o) sh[t] += sh[t + o];
        __syncthreads();
    }
    if (t == 0) out[0] = sh[0] * (1.0f / (float)BB);
}

extern "C" void kernel_launch(void* const* d_in, const int* in_sizes, int n_in,
                              void* d_out, int out_size)
{
    const float* em    = (const float*)d_in[0];
    const int*   tags  = (const int*)d_in[1];
    const int*   masks = (const int*)d_in[2];
    const float* start = (const float*)d_in[3];
    const float* endt  = (const float*)d_in[4];
    const float* trans = (const float*)d_in[5];
    float* out = (float*)d_out;

    crf_forward_kernel<<<BB / NB, FWD_THREADS>>>(em, masks, start, endt, trans);
    crf_num_kernel<<<BB, 128>>>(em, tags, masks, start, endt, trans);
    crf_reduce_kernel<<<1, BB>>>(out);
}

// round 14
// speedup vs baseline: 2.5391x; 2.5391x over previous
#include <cuda_runtime.h>
#include <cuda_bf16.h>

#define BB 512
#define SS 512
#define CC 96
#define NB 8                    // batches per CTA (one MMA N-tile)
#define FWD_THREADS 192         // 6 warps = 6 M-tiles of 16 states
#define SUP 104                 // u row pad (bf16) -> conflict-free B LDS
#define SEP 108                 // em row pad (f32) -> conflict-free epilogue LDS, 16B-mult

__device__ float g_num[BB];
__device__ float g_den[BB];

__device__ __forceinline__ float fast_rcp(float x) {
    float r;
    asm("rcp.approx.f32 %0, %1;" : "=f"(r) : "f"(x));
    return r;
}
__device__ __forceinline__ unsigned pack_bf16(float x, float y) {
    __nv_bfloat162 h = __floats2bfloat162_rn(x, y);
    return *reinterpret_cast<unsigned*>(&h);
}
__device__ __forceinline__ void mma_bf16(
    float& d0, float& d1, float& d2, float& d3,
    unsigned a0, unsigned a1, unsigned a2, unsigned a3,
    unsigned b0, unsigned b1)
{
    asm volatile(
        "mma.sync.aligned.m16n8k16.row.col.f32.bf16.bf16.f32 "
        "{%0,%1,%2,%3},{%4,%5,%6,%7},{%8,%9},{%0,%1,%2,%3};"
        : "+f"(d0), "+f"(d1), "+f"(d2), "+f"(d3)
        : "r"(a0), "r"(a1), "r"(a2), "r"(a3), "r"(b0), "r"(b1));
}
__device__ __forceinline__ void cp_async16(void* dst, const void* src) {
    unsigned d = (unsigned)__cvta_generic_to_shared(dst);
    asm volatile("cp.async.cg.shared.global [%0], [%1], 16;" :: "r"(d), "l"(src));
}
__device__ __forceinline__ void cp_async4(void* dst, const void* src) {
    unsigned d = (unsigned)__cvta_generic_to_shared(dst);
    asm volatile("cp.async.ca.shared.global [%0], [%1], 4;" :: "r"(d), "l"(src));
}
#define CP_COMMIT() asm volatile("cp.async.commit_group;" ::: "memory")
#define CP_WAIT2()  asm volatile("cp.async.wait_group 2;" ::: "memory")

// =====================================================================
// Forward via tensor cores (layout verified in R13), now with a
// depth-4 cp.async ring for em/masks (prefetch t+3) and a split MMA
// accumulator chain (3+3). One __syncthreads per step.
// =====================================================================
__global__ __launch_bounds__(FWD_THREADS, 1) void crf_forward_kernel(
    const float* __restrict__ em,
    const int* __restrict__ masks,
    const float* __restrict__ start,
    const float* __restrict__ endt,
    const float* __restrict__ trans)
{
    __shared__ __nv_bfloat16 s_u[2][NB][SUP];
    __shared__ __align__(16) float s_em[4][NB * SEP];
    __shared__ float s_r[2][NB];
    __shared__ int   s_mk[4][NB];
    __shared__ float s_ee[CC];
    __shared__ float s_S[NB];

    const int tid  = threadIdx.x;
    const int mt   = tid >> 5;          // M-tile (16 states) this warp owns
    const int lane = tid & 31;
    const int lr   = lane >> 2;         // 0..7
    const int lc   = lane & 3;          // 0..3
    const int b0g  = blockIdx.x * NB;

    // D-fragment cells this lane owns forever:
    const int s0 = 16 * mt + lr, s1 = s0 + 8;     // states
    const int n0 = 2 * lc, n1 = n0 + 1;           // batches (CTA-local)

    // cp.async mapping: thread covers 4 floats of em row n at offset s4
    const int cp_n = tid / 24, cp_s = (tid % 24) * 4;
    const float* em_src_base = em + (size_t)(b0g + cp_n) * SS * CC + cp_s;

    // ---- A fragments: A[m][k] = exp(trans[k][m])  (verified R13)
    unsigned A[6][4];
#pragma unroll
    for (int kt = 0; kt < 6; kt++) {
        int k0 = 16 * kt + 2 * lc;
        float a00 = __expf(trans[(k0 + 0) * CC + s0]);
        float a01 = __expf(trans[(k0 + 1) * CC + s0]);
        float a10 = __expf(trans[(k0 + 0) * CC + s1]);
        float a11 = __expf(trans[(k0 + 1) * CC + s1]);
        float a20 = __expf(trans[(k0 + 8) * CC + s0]);
        float a21 = __expf(trans[(k0 + 9) * CC + s0]);
        float a30 = __expf(trans[(k0 + 8) * CC + s1]);
        float a31 = __expf(trans[(k0 + 9) * CC + s1]);
        A[kt][0] = pack_bf16(a00, a01);
        A[kt][1] = pack_bf16(a10, a11);
        A[kt][2] = pack_bf16(a20, a21);
        A[kt][3] = pack_bf16(a30, a31);
    }

    // ---- t = 0 state
    float u00 = __expf(start[s0] + em[(size_t)(b0g + n0) * SS * CC + s0]);
    float u01 = __expf(start[s0] + em[(size_t)(b0g + n1) * SS * CC + s0]);
    float u10 = __expf(start[s1] + em[(size_t)(b0g + n0) * SS * CC + s1]);
    float u11 = __expf(start[s1] + em[(size_t)(b0g + n1) * SS * CC + s1]);
    s_u[0][n0][s0] = __float2bfloat16(u00);
    s_u[0][n1][s0] = __float2bfloat16(u01);
    s_u[0][n0][s1] = __float2bfloat16(u10);
    s_u[0][n1][s1] = __float2bfloat16(u11);
    float S0 = 0.f, S1 = 0.f;
    if (mt == 0 && lr == 0) {
        s_r[0][n0] = fast_rcp(u00);
        s_r[0][n1] = fast_rcp(u01);
    }
    if (tid < CC) s_ee[tid] = __expf(endt[tid]);

    // ---- prologue: stage em/mask for t = 1,2,3 (3 groups)
#pragma unroll
    for (int tt = 1; tt <= 3; tt++) {
        cp_async16(&s_em[tt & 3][cp_n * SEP + cp_s], em_src_base + (size_t)tt * CC);
        if (tid < NB) cp_async4(&s_mk[tt & 3][tid], masks + (size_t)(b0g + tid) * SS + tt);
        CP_COMMIT();
    }
    CP_WAIT2();          // group for t=1 done
    __syncthreads();

    int p = 0;
    for (int t = 1; t < SS; t++) {
        // issue prefetch for t+3 (always commit to keep group counting)
        int tp = t + 3;
        if (tp < SS) {
            cp_async16(&s_em[tp & 3][cp_n * SEP + cp_s], em_src_base + (size_t)tp * CC);
            if (tid < NB) cp_async4(&s_mk[tp & 3][tid], masks + (size_t)(b0g + tid) * SS + tp);
        }
        CP_COMMIT();

        const int eb = t & 3;

        // B fragments from bf16 u of previous step (verified R13)
        unsigned B0[6], B1[6];
#pragma unroll
        for (int kt = 0; kt < 6; kt++) {
            const __nv_bfloat16* up = &s_u[p][lr][16 * kt + 2 * lc];
            B0[kt] = *(const unsigned*)up;
            B1[kt] = *(const unsigned*)(up + 8);
        }

        // epilogue operands (issue loads early)
        float E00 = __expf(s_em[eb][n0 * SEP + s0]);
        float E01 = __expf(s_em[eb][n1 * SEP + s0]);
        float E10 = __expf(s_em[eb][n0 * SEP + s1]);
        float E11 = __expf(s_em[eb][n1 * SEP + s1]);
        float r0 = s_r[p][n0], r1 = s_r[p][n1];
        int m0 = s_mk[eb][n0], m1 = s_mk[eb][n1];

        // Q = expT^T @ U : two independent 3-deep MMA chains
        float d0 = 0.f, d1 = 0.f, d2 = 0.f, d3 = 0.f;
        float f0 = 0.f, f1 = 0.f, f2 = 0.f, f3 = 0.f;
#pragma unroll
        for (int kt = 0; kt < 3; kt++) {
            mma_bf16(d0, d1, d2, d3, A[kt][0], A[kt][1], A[kt][2], A[kt][3], B0[kt], B1[kt]);
            mma_bf16(f0, f1, f2, f3, A[kt + 3][0], A[kt + 3][1], A[kt + 3][2], A[kt + 3][3], B0[kt + 3], B1[kt + 3]);
        }
        d0 += f0; d1 += f1; d2 += f2; d3 += f3;

        // u_new = Q * exp(em) * r, masked update
        float v00 = d0 * (E00 * r0), v01 = d1 * (E01 * r1);
        float v10 = d2 * (E10 * r0), v11 = d3 * (E11 * r1);
        u00 = m0 ? v00 : u00;  u01 = m1 ? v01 : u01;
        u10 = m0 ? v10 : u10;  u11 = m1 ? v11 : u11;
        s_u[p ^ 1][n0][s0] = __float2bfloat16(u00);
        s_u[p ^ 1][n1][s0] = __float2bfloat16(u01);
        s_u[p ^ 1][n0][s1] = __float2bfloat16(u10);
        s_u[p ^ 1][n1][s1] = __float2bfloat16(u11);
        if (mt == 0 && lr == 0) {   // state-0 owners publish normalizers
            s_r[p ^ 1][n0] = m0 ? fast_rcp(u00) : r0;
            s_r[p ^ 1][n1] = m1 ? fast_rcp(u01) : r1;
            S0 = m0 ? S0 - __logf(r0) : S0;
            S1 = m1 ? S1 - __logf(r1) : S1;
        }

        CP_WAIT2();        // buffer t+1 arrived (visibility sealed by the barrier)
        __syncthreads();
        p ^= 1;
    }

    if (mt == 0 && lr == 0) { s_S[n0] = S0; s_S[n1] = S1; }
    __syncthreads();
    if (tid < NB) {
        float s = 0.f;
        for (int j = 0; j < CC; j++)
            s += __bfloat162float(s_u[p][tid][j]) * s_ee[j];
        g_den[b0g + tid] = s_S[tid] + __logf(s);
    }
}

// =====================================================================
// Numerator: one CTA (128 threads) per batch.
// =====================================================================
__global__ __launch_bounds__(128) void crf_num_kernel(
    const float* __restrict__ em,
    const int* __restrict__ tags,
    const int* __restrict__ masks,
    const float* __restrict__ start,
    const float* __restrict__ endt,
    const float* __restrict__ trans)
{
    const int b = blockIdx.x;
    const int tid = threadIdx.x;
    const int* tg = tags + (size_t)b * SS;
    const int* mk = masks + (size_t)b * SS;
    const float* e = em + (size_t)b * SS * CC;

    float s = 0.f;
    int cnt = 0;
#pragma unroll
    for (int it = 0; it < SS / 128; it++) {
        int t = tid + it * 128;
        int tagt = tg[t];
        int m = mk[t];
        cnt += m ? 1 : 0;
        if (t == 0) {
            s += start[tagt] + e[tagt];
        } else if (m) {
            int tp = tg[t - 1];
            s += trans[tp * CC + tagt] + e[(size_t)t * CC + tagt];
        }
    }
    __shared__ float ss[4];
    __shared__ int sc[4];
#pragma unroll
    for (int o = 16; o; o >>= 1) {
        s += __shfl_xor_sync(0xFFFFFFFFu, s, o);
        cnt += __shfl_xor_sync(0xFFFFFFFFu, cnt, o);
    }
    int wv = tid >> 5, lane = tid & 31;
    if (lane == 0) { ss[wv] = s; sc[wv] = cnt; }
    __syncthreads();
    if (tid == 0) {
        float st = ss[0] + ss[1] + ss[2] + ss[3];
        int ct = sc[0] + sc[1] + sc[2] + sc[3];
        int lt = tg[ct - 1];
        g_num[b] = st + endt[lt];
    }
}

// =====================================================================
// Final mean reduce
// =====================================================================
__global__ void crf_reduce_kernel(float* __restrict__ out)
{
    __shared__ float sh[BB];
    int t = threadIdx.x;
    sh[t] = g_num[t] - g_den[t];
    __syncthreads();
#pragma unroll
    for (int o = BB / 2; o > 0; o >>= 1) {
        if (t < o) sh[t] += sh[t + o];
        __syncthreads();
    }
    if (t == 0) out[0] = sh[0] * (1.0f / (float)BB);
}

extern "C" void kernel_launch(void* const* d_in, const int* in_sizes, int n_in,
                              void* d_out, int out_size)
{
    const float* em    = (const float*)d_in[0];
    const int*   tags  = (const int*)d_in[1];
    const int*   masks = (const int*)d_in[2];
    const float* start = (const float*)d_in[3];
    const float* endt  = (const float*)d_in[4];
    const float* trans = (const float*)d_in[5];
    float* out = (float*)d_out;

    crf_forward_kernel<<<BB / NB, FWD_THREADS>>>(em, masks, start, endt, trans);
    crf_num_kernel<<<BB, 128>>>(em, tags, masks, start, endt, trans);
    crf_reduce_kernel<<<1, BB>>>(out);
}